// round 16
// baseline (speedup 1.0000x reference)
#include <cuda_runtime.h>
#include <cuda_fp16.h>
#include <cstdint>

#define BSZ 2
#define SEQ 2048
#define DIM 1024
#define INNER 2048
#define HEADS 8
#define STATE 64
#define HDIM 256
#define MTOT (BSZ*SEQ)
#define NCHUNK 32
#define QC 64

// ---------------- scratch ---------------------------------------------------
__device__ float g_Bm[MTOT*HEADS*STATE];
__device__ float g_Cm[MTOT*HEADS*STATE];
__device__ float g_Dt[MTOT*HEADS];
__device__ float g_cdec[BSZ*HEADS*NCHUNK];
__device__ float g_pstats[BSZ*HEADS*NCHUNK*2];
__device__ float g_stats[BSZ*HEADS*2];

__device__ __half g_i_h [MTOT*DIM];
__device__ __half g_x_h [MTOT*INNER];
__device__ __half g_z_h [MTOT*INNER];
__device__ __half g_xa_h[MTOT*INNER];
__device__ __half g_y_h [MTOT*INNER];
__device__ __half g_g_h [MTOT*INNER];
__device__ __half g_wx_h[INNER*DIM];
__device__ __half g_wz_h[INNER*DIM];
__device__ __half g_wb_h[HEADS*STATE*INNER];
__device__ __half g_wc_h[HEADS*STATE*INNER];
__device__ __half g_wo_h[DIM*INNER];
__device__ __half g_Sc[BSZ*HEADS*NCHUNK*STATE*HDIM];
__device__ __half g_Sr[BSZ*HEADS*NCHUNK*STATE*HDIM];

// ---------------- helpers ----------------------------------------------------
__device__ __forceinline__ uint32_t smem_u32(const void* p) {
    uint32_t a;
    asm("{ .reg .u64 t; cvta.to.shared.u64 t, %1; cvt.u32.u64 %0, t; }" : "=r"(a) : "l"(p));
    return a;
}
#define CP_ASYNC16(dst, src) \
    asm volatile("cp.async.cg.shared.global [%0], [%1], 16;" :: "r"(dst), "l"(src))
#define CP_COMMIT()  asm volatile("cp.async.commit_group;" ::: "memory")
#define CP_WAIT0()   asm volatile("cp.async.wait_group 0;" ::: "memory")
#define CP_WAIT1()   asm volatile("cp.async.wait_group 1;" ::: "memory")

__device__ __forceinline__ void ldm_x4(uint32_t* r, uint32_t a) {
    asm volatile("ldmatrix.sync.aligned.m8n8.x4.shared.b16 {%0,%1,%2,%3}, [%4];"
        : "=r"(r[0]), "=r"(r[1]), "=r"(r[2]), "=r"(r[3]) : "r"(a));
}
__device__ __forceinline__ void ldm_x4t(uint32_t* r, uint32_t a) {
    asm volatile("ldmatrix.sync.aligned.m8n8.x4.trans.shared.b16 {%0,%1,%2,%3}, [%4];"
        : "=r"(r[0]), "=r"(r[1]), "=r"(r[2]), "=r"(r[3]) : "r"(a));
}
__device__ __forceinline__ void mma16816(float* c, const uint32_t* a, const uint32_t* b) {
    asm volatile("mma.sync.aligned.m16n8k16.row.col.f32.f16.f16.f32 "
        "{%0,%1,%2,%3}, {%4,%5,%6,%7}, {%8,%9}, {%0,%1,%2,%3};"
        : "+f"(c[0]), "+f"(c[1]), "+f"(c[2]), "+f"(c[3])
        : "r"(a[0]), "r"(a[1]), "r"(a[2]), "r"(a[3]), "r"(b[0]), "r"(b[1]));
}
__device__ __forceinline__ uint32_t sw128(uint32_t b) { return b ^ ((b >> 3) & 0x70); }
__device__ __forceinline__ uint32_t swx(uint32_t s, uint32_t pb) {
    return s * 512 + (pb ^ ((s & 7) << 4));
}

// ---------------- all fp32->fp16 converts in ONE kernel -----------------------
__global__ __launch_bounds__(256) void cvt_all(
    const float* s0, __half* d0, const float* s1, __half* d1,
    const float* s2, __half* d2, const float* s3, __half* d3,
    const float* s4, __half* d4, const float* s5, __half* d5)
{
    int b = blockIdx.x;
    const float* s; __half* d; long i;
    if      (b <  4096) { s = s0; d = d0; i = (long)b         * 256 + threadIdx.x; }
    else if (b <  6144) { s = s1; d = d1; i = (long)(b-4096)  * 256 + threadIdx.x; }
    else if (b <  8192) { s = s2; d = d2; i = (long)(b-6144)  * 256 + threadIdx.x; }
    else if (b <  9216) { s = s3; d = d3; i = (long)(b-8192)  * 256 + threadIdx.x; }
    else if (b < 10240) { s = s4; d = d4; i = (long)(b-9216)  * 256 + threadIdx.x; }
    else                { s = s5; d = d5; i = (long)(b-10240) * 256 + threadIdx.x; }
    float4 v = ((const float4*)s)[i];
    __half2* H = (__half2*)d;
    H[2*i]   = __halves2half2(__float2half_rn(v.x), __float2half_rn(v.y));
    H[2*i+1] = __halves2half2(__float2half_rn(v.z), __float2half_rn(v.w));
}

// ---------------- fp16 GEMM 128x128, GK=64, 3-stage ---------------------------
#define GK 64
#define A_TILE 16384
#define STAGE128 (2*A_TILE)
#define NSTAGE 3

__device__ __forceinline__ void load128(uint32_t stageb,
    const __half* __restrict__ A, const __half* __restrict__ W,
    int K, int k0, int tid)
{
    #pragma unroll
    for (int p = 0; p < 4; p++) {
        int u = p * 256 + tid;  int r = u >> 3, c8 = u & 7;
        uint32_t bo = (uint32_t)(r * 128 + c8 * 16);
        CP_ASYNC16(stageb + sw128(bo), A + (long)r * K + k0 + c8 * 8);
    }
    #pragma unroll
    for (int p = 0; p < 4; p++) {
        int u = p * 256 + tid;  int r = u >> 3, c8 = u & 7;
        uint32_t bo = (uint32_t)(r * 128 + c8 * 16);
        CP_ASYNC16(stageb + A_TILE + sw128(bo), W + (long)r * K + k0 + c8 * 8);
    }
}

__global__ __launch_bounds__(256, 2) void gemm128(int N, int K,
    const __half* __restrict__ A, const __half* __restrict__ W,
    float* __restrict__ C, const __half* __restrict__ W2, float* __restrict__ C2,
    int z0_half, int z1_half)
{
    int hout = z0_half;
    if (blockIdx.z == 1) { W = W2; C = C2; hout = z1_half; }
    const int bm = blockIdx.y * 128, bn = blockIdx.x * 128;
    const int tid = threadIdx.x, wid = tid >> 5, lane = tid & 31;
    const int wm = (wid & 1) * 64, wn = (wid >> 1) * 32;
    extern __shared__ char dsm[];
    const uint32_t tb = (smem_u32(dsm) + 1023) & ~1023u;
    const __half* Ap = A + (long)bm * K;
    const __half* Wp = W + (long)bn * K;

    float acc[4][4][4];
    #pragma unroll
    for (int mi = 0; mi < 4; mi++)
        #pragma unroll
        for (int ni = 0; ni < 4; ni++)
            #pragma unroll
            for (int q = 0; q < 4; q++) acc[mi][ni][q] = 0.f;

    const int la = lane & 15, ha = lane >> 4;
    const int wrow = (lane >> 4) * 8 + (lane & 7), wkh = (lane >> 3) & 1;

    const int NC = K / GK;
    load128(tb,            Ap, Wp, K, 0,  tid);  CP_COMMIT();
    load128(tb + STAGE128, Ap, Wp, K, GK, tid);  CP_COMMIT();

    for (int c = 0; c < NC; c++) {
        if (c + 1 < NC) { CP_WAIT1(); } else { CP_WAIT0(); }
        __syncthreads();
        if (c + 2 < NC) {
            load128(tb + ((c + 2) % NSTAGE) * STAGE128, Ap, Wp, K, (c + 2) * GK, tid);
            CP_COMMIT();
        }
        const uint32_t bufb = tb + (c % NSTAGE) * STAGE128;
        #pragma unroll
        for (int ks = 0; ks < 4; ks++) {
            uint32_t af[4][4], wf[4][2];
            #pragma unroll
            for (int mi = 0; mi < 4; mi++)
                ldm_x4(af[mi], bufb + sw128((uint32_t)((wm + mi*16 + la)*128 + ks*32 + ha*16)));
            #pragma unroll
            for (int pr = 0; pr < 2; pr++) {
                uint32_t t4[4];
                ldm_x4(t4, bufb + A_TILE + sw128((uint32_t)((wn + pr*16 + wrow)*128 + ks*32 + wkh*16)));
                wf[2*pr][0] = t4[0];  wf[2*pr][1] = t4[1];
                wf[2*pr+1][0] = t4[2]; wf[2*pr+1][1] = t4[3];
            }
            #pragma unroll
            for (int mi = 0; mi < 4; mi++)
                #pragma unroll
                for (int ni = 0; ni < 4; ni++)
                    mma16816(acc[mi][ni], af[mi], wf[ni]);
        }
    }

    const int r0 = bm + wm + (lane >> 2);
    const int c0 = bn + wn + (lane & 3) * 2;
    if (!hout) {
        #pragma unroll
        for (int mi = 0; mi < 4; mi++)
            #pragma unroll
            for (int ni = 0; ni < 4; ni++) {
                float* p = C + (long)(r0 + mi * 16) * N + c0 + ni * 8;
                *(float2*)p                 = make_float2(acc[mi][ni][0], acc[mi][ni][1]);
                *(float2*)(p + (long)8 * N) = make_float2(acc[mi][ni][2], acc[mi][ni][3]);
            }
    } else {
        __half* Ch = (__half*)C;
        #pragma unroll
        for (int mi = 0; mi < 4; mi++)
            #pragma unroll
            for (int ni = 0; ni < 4; ni++) {
                __half* p = Ch + (long)(r0 + mi * 16) * N + c0 + ni * 8;
                *(__half2*)p = __halves2half2(__float2half_rn(acc[mi][ni][0]),
                                              __float2half_rn(acc[mi][ni][1]));
                *(__half2*)(p + (long)8 * N) = __halves2half2(__float2half_rn(acc[mi][ni][2]),
                                                              __float2half_rn(acc[mi][ni][3]));
            }
    }
}

// ---------------- conv + SiLU + dt (fused, one row per block) -----------------
__global__ __launch_bounds__(512) void conv_dt_kernel(
    const __half* __restrict__ X, const float* __restrict__ conv_w,
    const float* __restrict__ conv_b, const float* __restrict__ Wdt,
    const float* __restrict__ b_dt, __half* __restrict__ xh,
    float* __restrict__ dto)
{
    const int m = blockIdx.x;
    const int t = m & (SEQ - 1);
    const int tid = threadIdx.x;
    const int c0 = tid * 4;
    __shared__ __align__(16) float sxa[INNER];

    const long base = (long)m * INNER + c0;
    float4 b4 = *(const float4*)(conv_b + c0);
    float a0 = b4.x, a1 = b4.y, a2 = b4.z, a3 = b4.w;
    float4 w0 = *(const float4*)(conv_w + (c0 + 0) * 4);
    float4 w1 = *(const float4*)(conv_w + (c0 + 1) * 4);
    float4 w2 = *(const float4*)(conv_w + (c0 + 2) * 4);
    float4 w3 = *(const float4*)(conv_w + (c0 + 3) * 4);
    const float k0[4] = {w0.x, w0.y, w0.z, w0.w};
    const float k1[4] = {w1.x, w1.y, w1.z, w1.w};
    const float k2[4] = {w2.x, w2.y, w2.z, w2.w};
    const float k3[4] = {w3.x, w3.y, w3.z, w3.w};
    #pragma unroll
    for (int k = 0; k < 4; k++) {
        if (t - 3 + k >= 0) {
            uint2 xv = *(const uint2*)(X + base + (long)(k - 3) * INNER);
            float2 x01 = __half22float2(*(__half2*)&xv.x);
            float2 x23 = __half22float2(*(__half2*)&xv.y);
            a0 += x01.x * k0[k];  a1 += x01.y * k1[k];
            a2 += x23.x * k2[k];  a3 += x23.y * k3[k];
        }
    }
    float s0 = a0 / (1.f + expf(-a0)),  s1 = a1 / (1.f + expf(-a1));
    float s2 = a2 / (1.f + expf(-a2)),  s3 = a3 / (1.f + expf(-a3));
    __half2* H = (__half2*)(xh + base);
    H[0] = __halves2half2(__float2half_rn(s0), __float2half_rn(s1));
    H[1] = __halves2half2(__float2half_rn(s2), __float2half_rn(s3));
    *(float4*)(sxa + c0) = make_float4(s0, s1, s2, s3);
    __syncthreads();

    const int w = tid >> 5, lane = tid & 31;
    if (w < HEADS) {
        const float4* wr = (const float4*)(Wdt + (long)w * INNER);
        const float4* xr = (const float4*)sxa;
        float s = 0.f;
        #pragma unroll 4
        for (int k = lane; k < INNER / 4; k += 32) {
            float4 xv = xr[k], wv = wr[k];
            s += xv.x * wv.x + xv.y * wv.y + xv.z * wv.z + xv.w * wv.w;
        }
        #pragma unroll
        for (int o = 16; o > 0; o >>= 1) s += __shfl_xor_sync(0xffffffffu, s, o);
        if (lane == 0) {
            float u = s + b_dt[w];
            dto[(long)m * HEADS + w] = (u > 20.f) ? u : log1pf(expf(u));
        }
    }
}

// ---------------- state: S_c = (cd*em*B)^T @ X (256 thr, ph split) ------------
#define S1_W 0
#define S1_X 8192
#define S1_SMEM 40960

__global__ __launch_bounds__(256) void state_kernel(
    const __half* __restrict__ xah, const float* __restrict__ bmat,
    const float* __restrict__ dtm, const float* __restrict__ log_a,
    __half* __restrict__ sch, float* __restrict__ cdec)
{
    const int chunk = blockIdx.x, bh = blockIdx.y, b = bh >> 3, h = bh & 7;
    const long m0 = (long)b * SEQ + chunk * QC;
    const int tid = threadIdx.x, wid = tid >> 5, lane = tid & 31;
    const int wid4 = wid & 3, ph = wid >> 2;
    extern __shared__ char smc[];
    const uint32_t sb = smem_u32(smc);
    __shared__ float sdt[64], sem[64];
    __shared__ float s_cd;

    const float a = -expf(log_a[h]);
    if (tid < 64) sdt[tid] = dtm[(m0 + tid) * HEADS + h];
    __syncthreads();
    if (tid < 64) {
        float s = 0.f;
        for (int u = 0; u <= tid; u++) s += sdt[u];
        sem[tid] = sdt[tid] * expf(-s * a);
        if (tid == 63) s_cd = expf(s * a);
    }
    __syncthreads();
    const float cd = s_cd;
    if (tid == 0) cdec[bh * NCHUNK + chunk] = cd;

    for (int it = tid; it < 2048; it += 256) {
        int s = it >> 5, pc = it & 31;
        CP_ASYNC16(sb + S1_X + swx((uint32_t)s, (uint32_t)(pc * 16)),
                   xah + (m0 + s) * INNER + h * HDIM + pc * 8);
    }
    CP_COMMIT();

    for (int it = tid; it < 1024; it += 256) {
        int r = it >> 4, c = (it & 15) * 4;
        float4 bv = *(const float4*)(bmat + (m0 + r) * (HEADS*STATE) + h * STATE + c);
        float w = cd * sem[r];
        uint32_t bo = sw128((uint32_t)(r * 128 + c * 2));
        *(__half2*)(smc + S1_W + bo)     = __halves2half2(__float2half_rn(w*bv.x), __float2half_rn(w*bv.y));
        *(__half2*)(smc + S1_W + bo + 4) = __halves2half2(__float2half_rn(w*bv.z), __float2half_rn(w*bv.w));
    }
    CP_WAIT0();
    __syncthreads();

    const long scb = (long)(bh * NCHUNK + chunk) * (STATE * HDIM);
    float sc[16][4];
    #pragma unroll
    for (int ni = 0; ni < 16; ni++)
        #pragma unroll
        for (int q = 0; q < 4; q++) sc[ni][q] = 0.f;
    #pragma unroll
    for (int ks = 0; ks < 4; ks++) {
        uint32_t a4[4];
        uint32_t krow = (uint32_t)(ks*16 + (lane>>4)*8 + (lane&7));
        ldm_x4t(a4, sb + S1_W + sw128(krow*128 + (uint32_t)(wid4*32 + ((lane>>3)&1)*16)));
        uint32_t srow = (uint32_t)(ks*16 + ((lane>>3)&1)*8 + (lane&7));
        #pragma unroll
        for (int pt = 0; pt < 8; pt++) {
            uint32_t x4[4];
            ldm_x4t(x4, sb + S1_X + swx(srow, (uint32_t)((ph*16 + pt*2 + (lane>>4))*16)));
            uint32_t b0[2] = {x4[0], x4[1]}, b1[2] = {x4[2], x4[3]};
            mma16816(sc[2*pt], a4, b0);
            mma16816(sc[2*pt+1], a4, b1);
        }
    }
    const int n0 = wid4*16 + (lane >> 2);
    const int p0c = ph*128 + (lane & 3)*2;
    #pragma unroll
    for (int ni = 0; ni < 16; ni++) {
        __half* p = sch + scb + (long)n0 * HDIM + p0c + ni*8;
        *(__half2*)p = __halves2half2(__float2half_rn(sc[ni][0]), __float2half_rn(sc[ni][1]));
        *(__half2*)(p + 8 * HDIM) = __halves2half2(__float2half_rn(sc[ni][2]), __float2half_rn(sc[ni][3]));
    }
}

// ---------------- inter-chunk state scan (512 blocks, 1 half2/thread) ---------
__global__ __launch_bounds__(256) void inter_kernel(
    const __half* __restrict__ sch, const float* __restrict__ cdec,
    __half* __restrict__ srh)
{
    const int bh = blockIdx.x;
    const int tid = threadIdx.x;
    const int nn = tid >> 2;                          // 0..63 (state row)
    const int c2 = blockIdx.y * 4 + (tid & 3);        // half2 column 0..127
    const long lane_off = (long)nn * HDIM + c2 * 2;   // halves
    float r0 = 0.f, r1 = 0.f;

    for (int k = 0; k < NCHUNK; k++) {
        const long off = (long)(bh * NCHUNK + k) * (STATE * HDIM) + lane_off;
        const float cd = cdec[bh * NCHUNK + k];
        *(__half2*)(srh + off) = __halves2half2(__float2half_rn(r0), __float2half_rn(r1));
        float2 f = __half22float2(*(const __half2*)(sch + off));
        r0 = cd * r0 + f.x;
        r1 = cd * r1 + f.y;
    }
}

// ---------------- fused y (256 thr): Y = M@X + ep*(C@S_r) + dp*x --------------
#define Y_C 0
#define Y_B 8192
#define Y_M 16384
#define Y_X 24576
#define Y_S 57344
#define Y_SMEM 90112

__global__ __launch_bounds__(256) void y_kernel(
    const __half* __restrict__ xah, const float* __restrict__ bmat,
    const float* __restrict__ cmat, const float* __restrict__ dtm,
    const float* __restrict__ log_a, const float* __restrict__ d_param,
    const __half* __restrict__ srh, __half* __restrict__ yh,
    float* __restrict__ pstats)
{
    const int chunk = blockIdx.x, bh = blockIdx.y, b = bh >> 3, h = bh & 7;
    const long m0 = (long)b * SEQ + chunk * QC;
    const int tid = threadIdx.x, wid = tid >> 5, lane = tid & 31;
    const int wid4 = wid & 3, ph = wid >> 2;
    extern __shared__ char smc[];
    const uint32_t sb = smem_u32(smc);
    __shared__ float sdt[64], sep[64], sem[64], rs[256], rq[256];

    const float a = -expf(log_a[h]);
    const float dp = d_param[h];
    if (tid < 64) sdt[tid] = dtm[(m0 + tid) * HEADS + h];
    __syncthreads();
    if (tid < 64) {
        float s = 0.f;
        for (int u = 0; u <= tid; u++) s += sdt[u];
        sep[tid] = expf(s * a);
        sem[tid] = sdt[tid] * expf(-s * a);
    }

    const long srb = (long)(bh * NCHUNK + chunk) * (STATE * HDIM);
    for (int it = tid; it < 2048; it += 256) {
        int s = it >> 5, pc = it & 31;
        CP_ASYNC16(sb + Y_X + swx((uint32_t)s, (uint32_t)(pc * 16)),
                   xah + (m0 + s) * INNER + h * HDIM + pc * 8);
        CP_ASYNC16(sb + Y_S + swx((uint32_t)s, (uint32_t)(pc * 16)),
                   srh + srb + (long)s * HDIM + pc * 8);
    }
    CP_COMMIT();
    __syncthreads();

    for (int it = tid; it < 1024; it += 256) {
        int r = it >> 4, c = (it & 15) * 4;
        float4 cv = *(const float4*)(cmat + (m0 + r) * (HEADS*STATE) + h * STATE + c);
        float4 bv = *(const float4*)(bmat + (m0 + r) * (HEADS*STATE) + h * STATE + c);
        uint32_t bo = sw128((uint32_t)(r * 128 + c * 2));
        *(__half2*)(smc + Y_C + bo)     = __halves2half2(__float2half_rn(cv.x), __float2half_rn(cv.y));
        *(__half2*)(smc + Y_C + bo + 4) = __halves2half2(__float2half_rn(cv.z), __float2half_rn(cv.w));
        *(__half2*)(smc + Y_B + bo)     = __halves2half2(__float2half_rn(bv.x), __float2half_rn(bv.y));
        *(__half2*)(smc + Y_B + bo + 4) = __halves2half2(__float2half_rn(bv.z), __float2half_rn(bv.w));
    }
    __syncthreads();

    const int la = lane & 15, ha = lane >> 4;

    // G = C @ B^T + mask -> M   (ALL 8 warps: warp = (row-quad wid4, n-half ph))
    {
        const int wrow = (lane >> 4) * 8 + (lane & 7), wkh = (lane >> 3) & 1;
        float g[4][4];
        #pragma unroll
        for (int ni = 0; ni < 4; ni++)
            #pragma unroll
            for (int q = 0; q < 4; q++) g[ni][q] = 0.f;
        #pragma unroll
        for (int ks = 0; ks < 4; ks++) {
            uint32_t a4[4];
            ldm_x4(a4, sb + Y_C + sw128((uint32_t)((wid4*16 + la)*128 + ks*32 + ha*16)));
            #pragma unroll
            for (int pr = 0; pr < 2; pr++) {
                uint32_t t4[4];
                ldm_x4(t4, sb + Y_B + sw128((uint32_t)(((ph*2 + pr)*16 + wrow)*128 + ks*32 + wkh*16)));
                uint32_t b0[2] = {t4[0], t4[1]}, b1[2] = {t4[2], t4[3]};
                mma16816(g[2*pr], a4, b0);
                mma16816(g[2*pr+1], a4, b1);
            }
        }
        const int t0 = wid4*16 + (lane >> 2), s0 = ph*32 + (lane & 3)*2;
        #pragma unroll
        for (int ni = 0; ni < 4; ni++)
            #pragma unroll
            for (int hf = 0; hf < 2; hf++) {
                int t = t0 + hf*8, s = s0 + ni*8;
                float e = sep[t];
                float v0 = (s   <= t) ? g[ni][hf*2]   * e * sem[s]   : 0.f;
                float v1 = (s+1 <= t) ? g[ni][hf*2+1] * e * sem[s+1] : 0.f;
                *(__half2*)(smc + Y_M + sw128((uint32_t)(t*128 + s*2))) =
                    __halves2half2(__float2half_rn(v0), __float2half_rn(v1));
            }
    }
    CP_WAIT0();
    __syncthreads();

    float sum = 0.f, sq = 0.f;
    {
        float yc[16][4], zc[16][4];
        #pragma unroll
        for (int ni = 0; ni < 16; ni++)
            #pragma unroll
            for (int q = 0; q < 4; q++) { yc[ni][q] = 0.f; zc[ni][q] = 0.f; }
        #pragma unroll
        for (int ks = 0; ks < 4; ks++) {
            uint32_t a4m[4], a4c[4];
            uint32_t aoff = sw128((uint32_t)((wid4*16 + la)*128 + ks*32 + ha*16));
            ldm_x4(a4m, sb + Y_M + aoff);
            ldm_x4(a4c, sb + Y_C + aoff);
            uint32_t srow = (uint32_t)(ks*16 + ((lane>>3)&1)*8 + (lane&7));
            #pragma unroll
            for (int pt = 0; pt < 8; pt++) {
                uint32_t pby = (uint32_t)((ph*16 + pt*2 + (lane>>4))*16);
                uint32_t x4[4], s4[4];
                ldm_x4t(x4, sb + Y_X + swx(srow, pby));
                ldm_x4t(s4, sb + Y_S + swx(srow, pby));
                uint32_t xb0[2] = {x4[0], x4[1]}, xb1[2] = {x4[2], x4[3]};
                uint32_t sb0[2] = {s4[0], s4[1]}, sb1[2] = {s4[2], s4[3]};
                mma16816(yc[2*pt],   a4m, xb0);
                mma16816(yc[2*pt+1], a4m, xb1);
                mma16816(zc[2*pt],   a4c, sb0);
                mma16816(zc[2*pt+1], a4c, sb1);
            }
        }
        const int t0 = wid4*16 + (lane >> 2);
        const int p0c = ph*128 + (lane & 3)*2;
        #pragma unroll
        for (int ni = 0; ni < 16; ni++)
            #pragma unroll
            for (int hf = 0; hf < 2; hf++) {
                int t = t0 + hf*8;
                float e = sep[t];
                long off = (m0 + t) * INNER + h * HDIM + p0c + ni*8;
                float2 xv = __half22float2(*(const __half2*)(xah + off));
                float y0 = yc[ni][hf*2]   + e * zc[ni][hf*2]   + dp * xv.x;
                float y1 = yc[ni][hf*2+1] + e * zc[ni][hf*2+1] + dp * xv.y;
                *(__half2*)(yh + off) = __halves2half2(__float2half_rn(y0), __float2half_rn(y1));
                sum += y0 + y1;  sq += y0*y0 + y1*y1;
            }
    }

    rs[tid] = sum;  rq[tid] = sq;
    __syncthreads();
    for (int o = 128; o > 0; o >>= 1) {
        if (tid < o) { rs[tid] += rs[tid + o]; rq[tid] += rq[tid + o]; }
        __syncthreads();
    }
    if (tid == 0) {
        pstats[(bh * NCHUNK + chunk) * 2]     = rs[0];
        pstats[(bh * NCHUNK + chunk) * 2 + 1] = rq[0];
    }
}

__global__ void stats_kernel(const float* __restrict__ pstats, float* __restrict__ stats)
{
    const int bh = blockIdx.x, lane = threadIdx.x;
    float s = pstats[(bh * NCHUNK + lane) * 2];
    float q = pstats[(bh * NCHUNK + lane) * 2 + 1];
    #pragma unroll
    for (int o = 16; o > 0; o >>= 1) {
        s += __shfl_xor_sync(0xffffffffu, s, o);
        q += __shfl_xor_sync(0xffffffffu, q, o);
    }
    if (lane == 0) {
        const float invN = 1.f / (float)(SEQ * HDIM);
        float mean = s * invN;
        float var  = q * invN - mean * mean;
        stats[bh * 2]     = mean;
        stats[bh * 2 + 1] = rsqrtf(var + 1e-5f);
    }
}

// ---------------- gate --------------------------------------------------------
__global__ __launch_bounds__(256) void gate_cvt_kernel(
    const __half* __restrict__ yh, const __half* __restrict__ zh,
    const float* __restrict__ stats, const float* __restrict__ gn_w,
    const float* __restrict__ gn_b, __half* __restrict__ gh)
{
    long i = (long)blockIdx.x * 256 + threadIdx.x;
    long base = i * 4;
    int c0 = (int)(base & (INNER - 1));
    long m = base >> 11;
    int b = (int)(m >> 11);
    int h = c0 >> 8;
    float mean = stats[(b * HEADS + h) * 2];
    float istd = stats[(b * HEADS + h) * 2 + 1];
    const __half2* Yh = (const __half2*)yh;
    const __half2* Zh = (const __half2*)zh;
    float2 y01 = __half22float2(Yh[2*i]);
    float2 y23 = __half22float2(Yh[2*i+1]);
    float2 z01 = __half22float2(Zh[2*i]);
    float2 z23 = __half22float2(Zh[2*i+1]);
    float4 gw = *(const float4*)(gn_w + c0);
    float4 gb = *(const float4*)(gn_b + c0);
    float g0 = ((y01.x - mean) * istd * gw.x + gb.x) * (z01.x / (1.f + expf(-z01.x)));
    float g1 = ((y01.y - mean) * istd * gw.y + gb.y) * (z01.y / (1.f + expf(-z01.y)));
    float g2 = ((y23.x - mean) * istd * gw.z + gb.z) * (z23.x / (1.f + expf(-z23.x)));
    float g3 = ((y23.y - mean) * istd * gw.w + gb.w) * (z23.y / (1.f + expf(-z23.y)));
    __half2* H = (__half2*)gh;
    H[2*i]   = __halves2half2(__float2half_rn(g0), __float2half_rn(g1));
    H[2*i+1] = __halves2half2(__float2half_rn(g2), __float2half_rn(g3));
}

// ---------------- launcher ----------------------------------------------------
extern "C" void kernel_launch(void* const* d_in, const int* in_sizes, int n_in,
                              void* d_out, int out_size)
{
    const float* inp     = (const float*)d_in[0];
    const float* Wx      = (const float*)d_in[1];
    const float* Wz      = (const float*)d_in[2];
    const float* conv_w  = (const float*)d_in[3];
    const float* conv_b  = (const float*)d_in[4];
    const float* Wb      = (const float*)d_in[5];
    const float* Wc      = (const float*)d_in[6];
    const float* Wdt     = (const float*)d_in[7];
    const float* b_dt    = (const float*)d_in[8];
    const float* log_a   = (const float*)d_in[9];
    const float* d_param = (const float*)d_in[10];
    const float* gn_w    = (const float*)d_in[11];
    const float* gn_b    = (const float*)d_in[12];
    const float* Wout    = (const float*)d_in[13];
    float* out = (float*)d_out;

    float *pB, *pC, *pDt, *pCD, *pPS, *pS;
    cudaGetSymbolAddress((void**)&pB,  g_Bm);
    cudaGetSymbolAddress((void**)&pC,  g_Cm);
    cudaGetSymbolAddress((void**)&pDt, g_Dt);
    cudaGetSymbolAddress((void**)&pCD, g_cdec);
    cudaGetSymbolAddress((void**)&pPS, g_pstats);
    cudaGetSymbolAddress((void**)&pS,  g_stats);

    __half *ih,*xhp,*zh,*xah,*yhh,*gh,*wxh,*wzh,*wbh,*wch,*woh,*psc,*psr;
    cudaGetSymbolAddress((void**)&ih,  g_i_h);
    cudaGetSymbolAddress((void**)&xhp, g_x_h);
    cudaGetSymbolAddress((void**)&zh,  g_z_h);
    cudaGetSymbolAddress((void**)&xah, g_xa_h);
    cudaGetSymbolAddress((void**)&yhh, g_y_h);
    cudaGetSymbolAddress((void**)&gh,  g_g_h);
    cudaGetSymbolAddress((void**)&wxh, g_wx_h);
    cudaGetSymbolAddress((void**)&wzh, g_wz_h);
    cudaGetSymbolAddress((void**)&wbh, g_wb_h);
    cudaGetSymbolAddress((void**)&wch, g_wc_h);
    cudaGetSymbolAddress((void**)&woh, g_wo_h);
    cudaGetSymbolAddress((void**)&psc, g_Sc);
    cudaGetSymbolAddress((void**)&psr, g_Sr);

    const int SMEM128 = NSTAGE * STAGE128 + 1024;
    cudaFuncSetAttribute(gemm128, cudaFuncAttributeMaxDynamicSharedMemorySize, SMEM128);
    cudaFuncSetAttribute(state_kernel, cudaFuncAttributeMaxDynamicSharedMemorySize, S1_SMEM);
    cudaFuncSetAttribute(y_kernel, cudaFuncAttributeMaxDynamicSharedMemorySize, Y_SMEM);

    const long NE = (long)MTOT * INNER;
    const int  EW4_BLOCKS = (int)(NE / 4 / 256);

    cvt_all<<<12288, 256>>>(inp, ih, Wx, wxh, Wz, wzh, Wb, wbh, Wc, wch, Wout, woh);

    gemm128<<<dim3(INNER/128, MTOT/128, 2), 256, SMEM128>>>(
        INNER, DIM, ih, wxh, (float*)xhp, wzh, (float*)zh, 1, 1);

    conv_dt_kernel<<<MTOT, 512>>>(xhp, conv_w, conv_b, Wdt, b_dt, xah, pDt);

    gemm128<<<dim3((HEADS*STATE)/128, MTOT/128, 2), 256, SMEM128>>>(
        HEADS*STATE, INNER, xah, wbh, pB, wch, pC, 0, 0);

    state_kernel<<<dim3(NCHUNK, BSZ*HEADS), 256, S1_SMEM>>>(
        xah, pB, pDt, log_a, psc, pCD);
    inter_kernel<<<dim3(BSZ*HEADS, 32), 256>>>(psc, pCD, psr);
    y_kernel<<<dim3(NCHUNK, BSZ*HEADS), 256, Y_SMEM>>>(
        xah, pB, pC, pDt, log_a, d_param, psr, yhh, pPS);
    stats_kernel<<<BSZ*HEADS, 32>>>(pPS, pS);

    gate_cvt_kernel<<<EW4_BLOCKS, 256>>>(yhh, zh, pS, gn_w, gn_b, gh);

    gemm128<<<dim3(DIM/128, MTOT/128, 1), 256, SMEM128>>>(
        DIM, INNER, gh, woh, out, woh, out, 0, 0);
}